// round 15
// baseline (speedup 1.0000x reference)
#include <cuda_runtime.h>
#include <cuda_fp16.h>
#include <math.h>
#include <stdint.h>

// Problem constants
constexpr int B  = 4;
constexpr int T  = 1024;
constexpr int E  = 1024;
constexpr int H  = 16;
constexpr int BT = B * T;              // 4096 rows
constexpr float EPS = 1e-5f;
constexpr float SCALE = 0.03125f;      // E^-0.5 = 1/32

// ---------------- scratch (no cudaMalloc allowed) ----------------
__device__ __half g_ln[3][BT * E];     // fp16 LN outputs [m][k]
__device__ __half g_wT[4][E * E];      // fp16 TRANSPOSED weights [n][k]
__device__ __half g_proj[3][BT * E];   // fp16 projected q/k/v [bt][h*64+d]
__device__ __half g_att[BT * E];       // fp16 attention out [bt][e]

// ---------------- helpers ----------------
__device__ __forceinline__ uint32_t h2u(__half2 h) { return *(uint32_t*)&h; }
__device__ __forceinline__ uint32_t h2ex2(uint32_t x) {
    uint32_t y; asm("ex2.approx.f16x2 %0, %1;" : "=r"(y) : "r"(x)); return y;
}
__device__ __forceinline__ void mma16(float* c, const uint32_t* a, const uint32_t* b) {
    asm volatile(
        "mma.sync.aligned.m16n8k16.row.col.f32.f16.f16.f32 "
        "{%0,%1,%2,%3}, {%4,%5,%6,%7}, {%8,%9}, {%0,%1,%2,%3};"
        : "+f"(c[0]), "+f"(c[1]), "+f"(c[2]), "+f"(c[3])
        : "r"(a[0]), "r"(a[1]), "r"(a[2]), "r"(a[3]), "r"(b[0]), "r"(b[1]));
}
__device__ __forceinline__ void ldsm_x4(uint32_t& r0, uint32_t& r1,
                                        uint32_t& r2, uint32_t& r3, uint32_t addr) {
    asm volatile("ldmatrix.sync.aligned.m8n8.x4.shared.b16 {%0,%1,%2,%3}, [%4];"
        : "=r"(r0), "=r"(r1), "=r"(r2), "=r"(r3) : "r"(addr));
}
__device__ __forceinline__ void ldsm_x4_t(uint32_t& r0, uint32_t& r1,
                                          uint32_t& r2, uint32_t& r3, uint32_t addr) {
    asm volatile("ldmatrix.sync.aligned.m8n8.x4.trans.shared.b16 {%0,%1,%2,%3}, [%4];"
        : "=r"(r0), "=r"(r1), "=r"(r2), "=r"(r3) : "r"(addr));
}
__device__ __forceinline__ void ldsm_x2_t(uint32_t& r0, uint32_t& r1, uint32_t addr) {
    asm volatile("ldmatrix.sync.aligned.m8n8.x2.trans.shared.b16 {%0,%1}, [%2];"
        : "=r"(r0), "=r"(r1) : "r"(addr));
}
__device__ __forceinline__ void cpasync16(void* s, const void* g) {
    uint32_t sa = (uint32_t)__cvta_generic_to_shared(s);
    asm volatile("cp.async.ca.shared.global [%0], [%1], 16;" :: "r"(sa), "l"(g));
}
#define CP_COMMIT() asm volatile("cp.async.commit_group;")
#define CP_WAIT0()  asm volatile("cp.async.wait_group 0;")
#define CP_WAIT1()  asm volatile("cp.async.wait_group 1;")

// ---------------- weight transpose + fp16 convert ----------------
__global__ void __launch_bounds__(256) round_wT(
    const float* __restrict__ wq, const float* __restrict__ wk,
    const float* __restrict__ wv, const float* __restrict__ wp)
{
    __shared__ float tile[32][33];
    int which = blockIdx.z;
    const float* src = (which == 0) ? wq : (which == 1) ? wk : (which == 2) ? wv : wp;
    __half* dst = g_wT[which];
    int k0 = blockIdx.y * 32, n0 = blockIdx.x * 32;
    int tx = threadIdx.x & 31, ty = threadIdx.x >> 5;
    #pragma unroll
    for (int i = 0; i < 4; i++)
        tile[ty + 8 * i][tx] = src[(size_t)(k0 + ty + 8 * i) * E + n0 + tx];
    __syncthreads();
    #pragma unroll
    for (int i = 0; i < 4; i++)
        dst[(size_t)(n0 + ty + 8 * i) * E + k0 + tx] = __float2half(tile[tx][ty + 8 * i]);
}

// ---------------- block reduction ----------------
__device__ __forceinline__ float block_sum_256(float v) {
    __shared__ float sh[8];
    int tid = threadIdx.x;
    #pragma unroll
    for (int o = 16; o; o >>= 1) v += __shfl_xor_sync(0xffffffffu, v, o);
    if ((tid & 31) == 0) sh[tid >> 5] = v;
    __syncthreads();
    float r = (tid < 8) ? sh[tid] : 0.f;
    if (tid < 32) {
        #pragma unroll
        for (int o = 4; o; o >>= 1) r += __shfl_xor_sync(0xffffffffu, r, o);
        if (tid == 0) sh[0] = r;
    }
    __syncthreads();
    r = sh[0];
    __syncthreads();
    return r;
}

// ---------------- LayerNorm -> fp16 ----------------
__global__ void __launch_bounds__(256) ln_kernel(
    const float* __restrict__ q, const float* __restrict__ k,
    const float* __restrict__ v, const float* __restrict__ gamma,
    const float* __restrict__ beta)
{
    int stream = blockIdx.y;
    int row    = blockIdx.x;
    const float* x = (stream == 0) ? q : (stream == 1) ? k : v;
    __half* y = g_ln[stream];
    x += (size_t)row * E;
    y += (size_t)row * E;
    int tid = threadIdx.x;

    float vals[4];
    float s = 0.f;
    #pragma unroll
    for (int i = 0; i < 4; i++) { vals[i] = x[tid + 256 * i]; s += vals[i]; }
    float mu = block_sum_256(s) * (1.f / E);

    float vs = 0.f;
    #pragma unroll
    for (int i = 0; i < 4; i++) { float d = vals[i] - mu; vs += d * d; }
    float var = block_sum_256(vs) * (1.f / E);
    float inv = rsqrtf(var + EPS);

    #pragma unroll
    for (int i = 0; i < 4; i++) {
        int e = tid + 256 * i;
        y[e] = __float2half((vals[i] - mu) * inv * gamma[e] + beta[e]);
    }
}

// ---------------- fp16 GEMM: CTA 128x256x64, 512 thr, 2-stage (unchanged) ----------------
constexpr int BM = 128, BN = 256, BK = 64;
constexpr int AS2 = 72;
constexpr int BS2 = 72;
constexpr int ABUF = BM * AS2;
constexpr int BBUF = BN * BS2;
constexpr int GEMM_SMEM = (2 * ABUF + 2 * BBUF) * (int)sizeof(__half);  // 110592

template<bool OUT>
__device__ __forceinline__ void gemm_body(
    const __half* __restrict__ A, const __half* __restrict__ Wt,
    const float* __restrict__ bias, void* __restrict__ Cv)
{
    extern __shared__ __half smh[];
    __half* As = smh;
    __half* Bs = smh + 2 * ABUF;
    uint32_t as_u = (uint32_t)__cvta_generic_to_shared(As);
    uint32_t bs_u = (uint32_t)__cvta_generic_to_shared(Bs);

    int m0 = blockIdx.y * BM, n0 = blockIdx.x * BN;
    int tid = threadIdx.x, lane = tid & 31, wid = tid >> 5;
    int g = lane >> 2, t = lane & 3;
    int wm = (wid & 1) * 64, wn = (wid >> 1) * 32;

    int lm = lane >> 3;
    int arow = (lm & 1) * 8 + (lane & 7), acol = (lm >> 1) * 8;
    int brow = (lm >> 1) * 8 + (lane & 7), bcol = (lm & 1) * 8;

    auto load_tiles = [&](int buf, int k0) {
        #pragma unroll
        for (int i = 0; i < 2; i++) {
            int idx = tid + i * 512; int r = idx >> 3, c8 = idx & 7;
            cpasync16(&As[buf * ABUF + r * AS2 + c8 * 8],
                      A + (size_t)(m0 + r) * E + k0 + c8 * 8);
        }
        #pragma unroll
        for (int i = 0; i < 4; i++) {
            int idx = tid + i * 512; int r = idx >> 3, c8 = idx & 7;
            cpasync16(&Bs[buf * BBUF + r * BS2 + c8 * 8],
                      Wt + (size_t)(n0 + r) * E + k0 + c8 * 8);
        }
        CP_COMMIT();
    };

    float acc[4][4][4] = {};
    load_tiles(0, 0);

    for (int kt = 0; kt < E / BK; kt++) {
        CP_WAIT0();
        __syncthreads();
        if (kt + 1 < E / BK) load_tiles((kt + 1) & 1, (kt + 1) * BK);
        uint32_t a_u = as_u + (kt & 1) * ABUF * 2;
        uint32_t b_u = bs_u + (kt & 1) * BBUF * 2;
        #pragma unroll
        for (int ks = 0; ks < 4; ks++) {
            int k0 = ks * 16;
            uint32_t af[4][4], bf[4][2];
            #pragma unroll
            for (int mt = 0; mt < 4; mt++)
                ldsm_x4(af[mt][0], af[mt][1], af[mt][2], af[mt][3],
                        a_u + (((wm + mt * 16 + arow) * AS2 + k0 + acol) << 1));
            #pragma unroll
            for (int i = 0; i < 2; i++)
                ldsm_x4(bf[2 * i][0], bf[2 * i][1], bf[2 * i + 1][0], bf[2 * i + 1][1],
                        b_u + (((wn + i * 16 + brow) * BS2 + k0 + bcol) << 1));
            #pragma unroll
            for (int mt = 0; mt < 4; mt++)
                #pragma unroll
                for (int nt = 0; nt < 4; nt++)
                    mma16(acc[mt][nt], af[mt], bf[nt]);
        }
    }

    #pragma unroll
    for (int mt = 0; mt < 4; mt++) {
        int r0 = m0 + wm + mt * 16 + g;
        #pragma unroll
        for (int nt = 0; nt < 4; nt++) {
            int c0 = n0 + wn + nt * 8 + 2 * t;
            if (OUT) {
                float* C = (float*)Cv;
                float b0 = bias[c0], b1 = bias[c0 + 1];
                float2 v;
                v.x = acc[mt][nt][0] + b0; v.y = acc[mt][nt][1] + b1;
                *(float2*)&C[(size_t)r0 * E + c0] = v;
                v.x = acc[mt][nt][2] + b0; v.y = acc[mt][nt][3] + b1;
                *(float2*)&C[(size_t)(r0 + 8) * E + c0] = v;
            } else {
                __half* C = (__half*)Cv;
                *(__half2*)&C[(size_t)r0 * E + c0] =
                    __floats2half2_rn(acc[mt][nt][0], acc[mt][nt][1]);
                *(__half2*)&C[(size_t)(r0 + 8) * E + c0] =
                    __floats2half2_rn(acc[mt][nt][2], acc[mt][nt][3]);
            }
        }
    }
}

__global__ void __launch_bounds__(512, 1) gemm_qkv() {
    int z = blockIdx.z;
    gemm_body<false>(g_ln[z], g_wT[z], nullptr, g_proj[z]);
}
__global__ void __launch_bounds__(512, 1) gemm_out(
    const float* __restrict__ bias, float* __restrict__ Cext) {
    gemm_body<true>(g_att, g_wT[3], bias, Cext);
}

// ---------------- fp16 flash attention: 256-row Q tile, 2 m-tiles/warp ----------------
constexpr int ST2 = 72;
constexpr int QROWS = 256;
constexpr int KVSTRIDE = 128 * ST2;         // K(64) + V(64) per stage, halves
constexpr int ATT_SMEM = (QROWS + 3 * 128) * ST2 * (int)sizeof(__half);  // 92160

__global__ void __launch_bounds__(256, 1) attn_tc() {
    extern __shared__ __half smh[];
    __half* Qs = smh;                        // [256][72]
    __half* KV = smh + QROWS * ST2;          // 3 stages: [K 64][V 64] each
    uint32_t kv_u = (uint32_t)__cvta_generic_to_shared(KV);

    int qt = (gridDim.x - 1) - blockIdx.x;   // descending work order
    int h = blockIdx.y, b = blockIdx.z;
    const __half* Q = g_proj[0] + ((size_t)b * T + qt * QROWS) * E + h * 64;
    const __half* K = g_proj[1] + (size_t)b * T * E + h * 64;
    const __half* V = g_proj[2] + (size_t)b * T * E + h * 64;

    int tid = threadIdx.x, lane = tid & 31, wid = tid >> 5;   // wid 0..7
    int g = lane >> 2, t = lane & 3;
    int lm = lane >> 3;
    int krow = (lm >> 1) * 8 + (lane & 7), kcol = (lm & 1) * 8;

    auto loadKV = [&](int buf, int kt) {
        __half* Kd = KV + buf * KVSTRIDE;
        __half* Vd = Kd + 64 * ST2;
        const __half* Kg = K + (size_t)(kt * 64) * E;
        const __half* Vg = V + (size_t)(kt * 64) * E;
        #pragma unroll
        for (int i = 0; i < 2; i++) {
            int idx = tid + i * 256; int r = idx >> 3, c8 = idx & 7;
            cpasync16(&Kd[r * ST2 + c8 * 8], Kg + (size_t)r * E + c8 * 8);
            cpasync16(&Vd[r * ST2 + c8 * 8], Vg + (size_t)r * E + c8 * 8);
        }
        CP_COMMIT();
    };

    int nkv = 4 * (qt + 1);

    // Q tile 256x64; ones-column pads for all 3 V stages
    #pragma unroll
    for (int i = 0; i < 8; i++) {
        int idx = tid + i * 256; int r = idx >> 3, c8 = idx & 7;
        *(uint4*)&Qs[r * ST2 + c8 * 8] = *(const uint4*)(Q + (size_t)r * E + c8 * 8);
    }
    if (tid < 64) {
        uint4 ones = {0x00003C00u, 0u, 0u, 0u};   // {1.0h, 0...}
        #pragma unroll
        for (int s = 0; s < 3; s++)
            *(uint4*)&KV[s * KVSTRIDE + 64 * ST2 + tid * ST2 + 64] = ones;
    }
    loadKV(0, 0);
    loadKV(1, 1);
    __syncthreads();

    // Q fragments for both m-tiles (rows mr0, mr1), scaled by SCALE*log2e
    const float QS = SCALE * 1.44269504f;
    uint32_t qf0[4][4], qf1[4][4];
    int mr0 = wid * 16, mr1 = 128 + wid * 16;
    #pragma unroll
    for (int ks = 0; ks < 4; ks++) {
        int k0 = ks * 16;
        #pragma unroll
        for (int j = 0; j < 4; j++) {
            int rr0 = (j & 1) ? 8 : 0;
            int cc  = (j & 2) ? 8 : 0;
            float2 f0 = __half22float2(*(const __half2*)&Qs[(mr0 + g + rr0) * ST2 + k0 + 2 * t + cc]);
            float2 f1 = __half22float2(*(const __half2*)&Qs[(mr1 + g + rr0) * ST2 + k0 + 2 * t + cc]);
            qf0[ks][j] = h2u(__floats2half2_rn(f0.x * QS, f0.y * QS));
            qf1[ks][j] = h2u(__floats2half2_rn(f1.x * QS, f1.y * QS));
        }
    }

    float o0[8][4] = {}, o1[8][4] = {};
    float lacc0[4] = {}, lacc1[4] = {};
    int row0 = qt * QROWS + mr0 + g;          // mt0 rows: row0, row0+8
    int row1 = row0 + 128;                    // mt1 rows
    int lim0  = (qt * QROWS + mr0 + 15) >> 6; // last kt with any unmasked mt0 element
    int mask0 = (qt * QROWS + mr0) >> 6;      // first kt possibly needing mt0 mask
    int mask1 = (qt * QROWS + 128 + mr0) >> 6;

    for (int kt = 0; kt < nkv; kt++) {
        if (kt + 1 < nkv) { CP_WAIT1(); } else { CP_WAIT0(); }
        __syncthreads();                       // stage kt ready; stage (kt-1)%3 free
        if (kt + 2 < nkv) loadKV((kt + 2) % 3, kt + 2);

        uint32_t kb_u = kv_u + (kt % 3) * KVSTRIDE * 2;
        uint32_t vb_u = kb_u + 64 * ST2 * 2;
        bool act0 = (kt <= lim0);             // mt1 is always active (lim1 = nkv-1)

        // S = Q @ K^T (K fragments shared by both m-tiles)
        float s0[8][4] = {}, s1[8][4] = {};
        #pragma unroll
        for (int ks = 0; ks < 4; ks++) {
            int k0 = ks * 16;
            uint32_t bf[8][2];
            #pragma unroll
            for (int i = 0; i < 4; i++)
                ldsm_x4(bf[2 * i][0], bf[2 * i][1], bf[2 * i + 1][0], bf[2 * i + 1][1],
                        kb_u + (((i * 16 + krow) * ST2 + k0 + kcol) << 1));
            #pragma unroll
            for (int nt = 0; nt < 8; nt++) {
                if (act0) mma16(s0[nt], qf0[ks], bf[nt]);
                mma16(s1[nt], qf1[ks], bf[nt]);
            }
        }

        // causal masks (elementwise, conservative trigger)
        if (act0 && kt >= mask0) {
            #pragma unroll
            for (int nt = 0; nt < 8; nt++) {
                int c = kt * 64 + nt * 8 + 2 * t;
                if (c     > row0)     s0[nt][0] = -1e30f;
                if (c + 1 > row0)     s0[nt][1] = -1e30f;
                if (c     > row0 + 8) s0[nt][2] = -1e30f;
                if (c + 1 > row0 + 8) s0[nt][3] = -1e30f;
            }
        }
        if (kt >= mask1) {
            #pragma unroll
            for (int nt = 0; nt < 8; nt++) {
                int c = kt * 64 + nt * 8 + 2 * t;
                if (c     > row1)     s1[nt][0] = -1e30f;
                if (c + 1 > row1)     s1[nt][1] = -1e30f;
                if (c     > row1 + 8) s1[nt][2] = -1e30f;
                if (c + 1 > row1 + 8) s1[nt][3] = -1e30f;
            }
        }

        // fixed-max softmax: p = 2^s in fp16x2 == PV A-fragments
        uint32_t af0[4][4], af1[4][4];
        #pragma unroll
        for (int ks = 0; ks < 4; ks++) {
            if (act0) {
                af0[ks][0] = h2ex2(h2u(__floats2half2_rn(s0[2 * ks][0],     s0[2 * ks][1])));
                af0[ks][1] = h2ex2(h2u(__floats2half2_rn(s0[2 * ks][2],     s0[2 * ks][3])));
                af0[ks][2] = h2ex2(h2u(__floats2half2_rn(s0[2 * ks + 1][0], s0[2 * ks + 1][1])));
                af0[ks][3] = h2ex2(h2u(__floats2half2_rn(s0[2 * ks + 1][2], s0[2 * ks + 1][3])));
            }
            af1[ks][0] = h2ex2(h2u(__floats2half2_rn(s1[2 * ks][0],     s1[2 * ks][1])));
            af1[ks][1] = h2ex2(h2u(__floats2half2_rn(s1[2 * ks][2],     s1[2 * ks][3])));
            af1[ks][2] = h2ex2(h2u(__floats2half2_rn(s1[2 * ks + 1][0], s1[2 * ks + 1][1])));
            af1[ks][3] = h2ex2(h2u(__floats2half2_rn(s1[2 * ks + 1][2], s1[2 * ks + 1][3])));
        }

        // O += P @ V ; l += P @ ones (V fragments shared by both m-tiles)
        #pragma unroll
        for (int ks = 0; ks < 4; ks++) {
            int k0 = ks * 16;
            #pragma unroll
            for (int ntp = 0; ntp < 4; ntp++) {
                uint32_t b0, b1, b2, b3;
                uint32_t addr = vb_u +
                    (((k0 + (lane & 15)) * ST2 + (ntp * 2 + (lane >> 4)) * 8) << 1);
                ldsm_x4_t(b0, b1, b2, b3, addr);
                uint32_t bfA[2] = {b0, b1}, bfB[2] = {b2, b3};
                if (act0) {
                    mma16(o0[ntp * 2],     af0[ks], bfA);
                    mma16(o0[ntp * 2 + 1], af0[ks], bfB);
                }
                mma16(o1[ntp * 2],     af1[ks], bfA);
                mma16(o1[ntp * 2 + 1], af1[ks], bfB);
            }
            uint32_t l0, l1;
            ldsm_x2_t(l0, l1, vb_u + (((k0 + (lane & 15)) * ST2 + 64) << 1));
            uint32_t bfl[2] = {l0, l1};
            if (act0) mma16(lacc0, af0[ks], bfl);
            mma16(lacc1, af1[ks], bfl);
        }
    }

    // broadcast l from t==0 lane of each quad
    float la0 = __shfl_sync(0xffffffffu, lacc0[0], lane & 28);
    float lb0 = __shfl_sync(0xffffffffu, lacc0[2], lane & 28);
    float la1 = __shfl_sync(0xffffffffu, lacc1[0], lane & 28);
    float lb1 = __shfl_sync(0xffffffffu, lacc1[2], lane & 28);
    float ia0 = 1.f / la0, ib0 = 1.f / lb0;
    float ia1 = 1.f / la1, ib1 = 1.f / lb1;
    __half* O0 = g_att + ((size_t)b * T + row0) * E + h * 64;
    __half* O1 = g_att + ((size_t)b * T + row1) * E + h * 64;
    #pragma unroll
    for (int nt = 0; nt < 8; nt++) {
        *(__half2*)&O0[nt * 8 + 2 * t] =
            __floats2half2_rn(o0[nt][0] * ia0, o0[nt][1] * ia0);
        *(__half2*)&O0[8 * (size_t)E + nt * 8 + 2 * t] =
            __floats2half2_rn(o0[nt][2] * ib0, o0[nt][3] * ib0);
        *(__half2*)&O1[nt * 8 + 2 * t] =
            __floats2half2_rn(o1[nt][0] * ia1, o1[nt][1] * ia1);
        *(__half2*)&O1[8 * (size_t)E + nt * 8 + 2 * t] =
            __floats2half2_rn(o1[nt][2] * ib1, o1[nt][3] * ib1);
    }
}

// ---------------- launch ----------------
extern "C" void kernel_launch(void* const* d_in, const int* in_sizes, int n_in,
                              void* d_out, int out_size)
{
    const float* v    = (const float*)d_in[0];
    const float* k    = (const float*)d_in[1];
    const float* q    = (const float*)d_in[2];
    const float* ln_g = (const float*)d_in[3];
    const float* ln_b = (const float*)d_in[4];
    const float* Wq   = (const float*)d_in[5];
    const float* Wk   = (const float*)d_in[6];
    const float* Wv   = (const float*)d_in[7];
    const float* Wp   = (const float*)d_in[8];
    const float* bp   = (const float*)d_in[9];
    float* out = (float*)d_out;

    cudaFuncSetAttribute(gemm_qkv, cudaFuncAttributeMaxDynamicSharedMemorySize, GEMM_SMEM);
    cudaFuncSetAttribute(gemm_out, cudaFuncAttributeMaxDynamicSharedMemorySize, GEMM_SMEM);
    cudaFuncSetAttribute(attn_tc,  cudaFuncAttributeMaxDynamicSharedMemorySize, ATT_SMEM);

    // 0) weight transpose->fp16 + LayerNorm->fp16
    round_wT<<<dim3(E / 32, E / 32, 4), 256>>>(Wq, Wk, Wv, Wp);
    ln_kernel<<<dim3(BT, 3), 256>>>(q, k, v, ln_g, ln_b);

    // 1) QKV projections (fp16, 512 thr, 2-stage), fused
    gemm_qkv<<<dim3(E / BN, BT / BM, 3), 512, GEMM_SMEM>>>();

    // 2) causal flash attention (256-row Q tiles, 2 m-tiles/warp)
    attn_tc<<<dim3(T / QROWS, H, B), 256, ATT_SMEM>>>();

    // 3) output projection + bias -> d_out
    gemm_out<<<dim3(E / BN, BT / BM), 512, GEMM_SMEM>>>(bp, out);
}

// round 16
// speedup vs baseline: 1.0432x; 1.0432x over previous
#include <cuda_runtime.h>
#include <cuda_fp16.h>
#include <math.h>
#include <stdint.h>

// Problem constants
constexpr int B  = 4;
constexpr int T  = 1024;
constexpr int E  = 1024;
constexpr int H  = 16;
constexpr int BT = B * T;              // 4096 rows
constexpr float EPS = 1e-5f;
constexpr float SCALE = 0.03125f;      // E^-0.5 = 1/32

// ---------------- scratch (no cudaMalloc allowed) ----------------
__device__ __half g_ln[3][BT * E];     // fp16 LN outputs [m][k]
__device__ __half g_wT[4][E * E];      // fp16 TRANSPOSED weights [n][k]
__device__ __half g_proj[3][BT * E];   // fp16 projected q/k/v [bt][h*64+d]
__device__ __half g_att[BT * E];       // fp16 attention out [bt][e]

// ---------------- helpers ----------------
__device__ __forceinline__ uint32_t h2u(__half2 h) { return *(uint32_t*)&h; }
__device__ __forceinline__ uint32_t h2ex2(uint32_t x) {
    uint32_t y; asm("ex2.approx.f16x2 %0, %1;" : "=r"(y) : "r"(x)); return y;
}
__device__ __forceinline__ void mma16(float* c, const uint32_t* a, const uint32_t* b) {
    asm volatile(
        "mma.sync.aligned.m16n8k16.row.col.f32.f16.f16.f32 "
        "{%0,%1,%2,%3}, {%4,%5,%6,%7}, {%8,%9}, {%0,%1,%2,%3};"
        : "+f"(c[0]), "+f"(c[1]), "+f"(c[2]), "+f"(c[3])
        : "r"(a[0]), "r"(a[1]), "r"(a[2]), "r"(a[3]), "r"(b[0]), "r"(b[1]));
}
__device__ __forceinline__ void ldsm_x4(uint32_t& r0, uint32_t& r1,
                                        uint32_t& r2, uint32_t& r3, uint32_t addr) {
    asm volatile("ldmatrix.sync.aligned.m8n8.x4.shared.b16 {%0,%1,%2,%3}, [%4];"
        : "=r"(r0), "=r"(r1), "=r"(r2), "=r"(r3) : "r"(addr));
}
__device__ __forceinline__ void ldsm_x4_t(uint32_t& r0, uint32_t& r1,
                                          uint32_t& r2, uint32_t& r3, uint32_t addr) {
    asm volatile("ldmatrix.sync.aligned.m8n8.x4.trans.shared.b16 {%0,%1,%2,%3}, [%4];"
        : "=r"(r0), "=r"(r1), "=r"(r2), "=r"(r3) : "r"(addr));
}
__device__ __forceinline__ void ldsm_x2_t(uint32_t& r0, uint32_t& r1, uint32_t addr) {
    asm volatile("ldmatrix.sync.aligned.m8n8.x2.trans.shared.b16 {%0,%1}, [%2];"
        : "=r"(r0), "=r"(r1) : "r"(addr));
}
__device__ __forceinline__ void cpasync16(void* s, const void* g) {
    uint32_t sa = (uint32_t)__cvta_generic_to_shared(s);
    asm volatile("cp.async.ca.shared.global [%0], [%1], 16;" :: "r"(sa), "l"(g));
}
#define CP_COMMIT() asm volatile("cp.async.commit_group;")
#define CP_WAIT0()  asm volatile("cp.async.wait_group 0;")
#define CP_WAIT1()  asm volatile("cp.async.wait_group 1;")

// ---------------- weight transpose + fp16 convert ----------------
__global__ void __launch_bounds__(256) round_wT(
    const float* __restrict__ wq, const float* __restrict__ wk,
    const float* __restrict__ wv, const float* __restrict__ wp)
{
    __shared__ float tile[32][33];
    int which = blockIdx.z;
    const float* src = (which == 0) ? wq : (which == 1) ? wk : (which == 2) ? wv : wp;
    __half* dst = g_wT[which];
    int k0 = blockIdx.y * 32, n0 = blockIdx.x * 32;
    int tx = threadIdx.x & 31, ty = threadIdx.x >> 5;
    #pragma unroll
    for (int i = 0; i < 4; i++)
        tile[ty + 8 * i][tx] = src[(size_t)(k0 + ty + 8 * i) * E + n0 + tx];
    __syncthreads();
    #pragma unroll
    for (int i = 0; i < 4; i++)
        dst[(size_t)(n0 + ty + 8 * i) * E + k0 + tx] = __float2half(tile[tx][ty + 8 * i]);
}

// ---------------- block reduction ----------------
__device__ __forceinline__ float block_sum_256(float v) {
    __shared__ float sh[8];
    int tid = threadIdx.x;
    #pragma unroll
    for (int o = 16; o; o >>= 1) v += __shfl_xor_sync(0xffffffffu, v, o);
    if ((tid & 31) == 0) sh[tid >> 5] = v;
    __syncthreads();
    float r = (tid < 8) ? sh[tid] : 0.f;
    if (tid < 32) {
        #pragma unroll
        for (int o = 4; o; o >>= 1) r += __shfl_xor_sync(0xffffffffu, r, o);
        if (tid == 0) sh[0] = r;
    }
    __syncthreads();
    r = sh[0];
    __syncthreads();
    return r;
}

// ---------------- LayerNorm -> fp16 ----------------
__global__ void __launch_bounds__(256) ln_kernel(
    const float* __restrict__ q, const float* __restrict__ k,
    const float* __restrict__ v, const float* __restrict__ gamma,
    const float* __restrict__ beta)
{
    int stream = blockIdx.y;
    int row    = blockIdx.x;
    const float* x = (stream == 0) ? q : (stream == 1) ? k : v;
    __half* y = g_ln[stream];
    x += (size_t)row * E;
    y += (size_t)row * E;
    int tid = threadIdx.x;

    float vals[4];
    float s = 0.f;
    #pragma unroll
    for (int i = 0; i < 4; i++) { vals[i] = x[tid + 256 * i]; s += vals[i]; }
    float mu = block_sum_256(s) * (1.f / E);

    float vs = 0.f;
    #pragma unroll
    for (int i = 0; i < 4; i++) { float d = vals[i] - mu; vs += d * d; }
    float var = block_sum_256(vs) * (1.f / E);
    float inv = rsqrtf(var + EPS);

    #pragma unroll
    for (int i = 0; i < 4; i++) {
        int e = tid + 256 * i;
        y[e] = __float2half((vals[i] - mu) * inv * gamma[e] + beta[e]);
    }
}

// ---------------- fp16 GEMM: CTA 128x256x64, 512 thr, 2-stage ----------------
constexpr int BM = 128, BN = 256, BK = 64;
constexpr int AS2 = 72;
constexpr int BS2 = 72;
constexpr int ABUF = BM * AS2;
constexpr int BBUF = BN * BS2;
constexpr int GEMM_SMEM = (2 * ABUF + 2 * BBUF) * (int)sizeof(__half);  // 110592

template<bool OUT>
__device__ __forceinline__ void gemm_body(
    const __half* __restrict__ A, const __half* __restrict__ Wt,
    const float* __restrict__ bias, void* __restrict__ Cv)
{
    extern __shared__ __half smh[];
    __half* As = smh;
    __half* Bs = smh + 2 * ABUF;
    uint32_t as_u = (uint32_t)__cvta_generic_to_shared(As);
    uint32_t bs_u = (uint32_t)__cvta_generic_to_shared(Bs);

    int m0 = blockIdx.y * BM, n0 = blockIdx.x * BN;
    int tid = threadIdx.x, lane = tid & 31, wid = tid >> 5;
    int g = lane >> 2, t = lane & 3;
    int wm = (wid & 1) * 64, wn = (wid >> 1) * 32;

    int lm = lane >> 3;
    int arow = (lm & 1) * 8 + (lane & 7), acol = (lm >> 1) * 8;
    int brow = (lm >> 1) * 8 + (lane & 7), bcol = (lm & 1) * 8;

    auto load_tiles = [&](int buf, int k0) {
        #pragma unroll
        for (int i = 0; i < 2; i++) {
            int idx = tid + i * 512; int r = idx >> 3, c8 = idx & 7;
            cpasync16(&As[buf * ABUF + r * AS2 + c8 * 8],
                      A + (size_t)(m0 + r) * E + k0 + c8 * 8);
        }
        #pragma unroll
        for (int i = 0; i < 4; i++) {
            int idx = tid + i * 512; int r = idx >> 3, c8 = idx & 7;
            cpasync16(&Bs[buf * BBUF + r * BS2 + c8 * 8],
                      Wt + (size_t)(n0 + r) * E + k0 + c8 * 8);
        }
        CP_COMMIT();
    };

    float acc[4][4][4] = {};
    load_tiles(0, 0);

    for (int kt = 0; kt < E / BK; kt++) {
        CP_WAIT0();
        __syncthreads();
        if (kt + 1 < E / BK) load_tiles((kt + 1) & 1, (kt + 1) * BK);
        uint32_t a_u = as_u + (kt & 1) * ABUF * 2;
        uint32_t b_u = bs_u + (kt & 1) * BBUF * 2;
        #pragma unroll
        for (int ks = 0; ks < 4; ks++) {
            int k0 = ks * 16;
            uint32_t af[4][4], bf[4][2];
            #pragma unroll
            for (int mt = 0; mt < 4; mt++)
                ldsm_x4(af[mt][0], af[mt][1], af[mt][2], af[mt][3],
                        a_u + (((wm + mt * 16 + arow) * AS2 + k0 + acol) << 1));
            #pragma unroll
            for (int i = 0; i < 2; i++)
                ldsm_x4(bf[2 * i][0], bf[2 * i][1], bf[2 * i + 1][0], bf[2 * i + 1][1],
                        b_u + (((wn + i * 16 + brow) * BS2 + k0 + bcol) << 1));
            #pragma unroll
            for (int mt = 0; mt < 4; mt++)
                #pragma unroll
                for (int nt = 0; nt < 4; nt++)
                    mma16(acc[mt][nt], af[mt], bf[nt]);
        }
    }

    #pragma unroll
    for (int mt = 0; mt < 4; mt++) {
        int r0 = m0 + wm + mt * 16 + g;
        #pragma unroll
        for (int nt = 0; nt < 4; nt++) {
            int c0 = n0 + wn + nt * 8 + 2 * t;
            if (OUT) {
                float* C = (float*)Cv;
                float b0 = bias[c0], b1 = bias[c0 + 1];
                float2 v;
                v.x = acc[mt][nt][0] + b0; v.y = acc[mt][nt][1] + b1;
                *(float2*)&C[(size_t)r0 * E + c0] = v;
                v.x = acc[mt][nt][2] + b0; v.y = acc[mt][nt][3] + b1;
                *(float2*)&C[(size_t)(r0 + 8) * E + c0] = v;
            } else {
                __half* C = (__half*)Cv;
                *(__half2*)&C[(size_t)r0 * E + c0] =
                    __floats2half2_rn(acc[mt][nt][0], acc[mt][nt][1]);
                *(__half2*)&C[(size_t)(r0 + 8) * E + c0] =
                    __floats2half2_rn(acc[mt][nt][2], acc[mt][nt][3]);
            }
        }
    }
}

__global__ void __launch_bounds__(512, 1) gemm_qkv() {
    int z = blockIdx.z;
    gemm_body<false>(g_ln[z], g_wT[z], nullptr, g_proj[z]);
}
__global__ void __launch_bounds__(512, 1) gemm_out(
    const float* __restrict__ bias, float* __restrict__ Cext) {
    gemm_body<true>(g_att, g_wT[3], bias, Cext);
}

// ---------------- fp16 flash attention: 128-row Q, 3-stage ring, hoisted ones-frag ----------------
constexpr int ST2 = 72;
constexpr int QROWS = 128;
constexpr int KVSTRIDE = 128 * ST2;         // K(64) + V(64) per stage, halves
constexpr int ATT_SMEM = (QROWS + 3 * 128) * ST2 * (int)sizeof(__half);  // 73728

__global__ void __launch_bounds__(256, 2) attn_tc() {
    extern __shared__ __half smh[];
    __half* Qs = smh;                        // [128][72]
    __half* KV = smh + QROWS * ST2;          // 3 stages: [K 64][V 64] each
    uint32_t kv_u = (uint32_t)__cvta_generic_to_shared(KV);

    int qt = (gridDim.x - 1) - blockIdx.x;   // descending work order
    int h = blockIdx.y, b = blockIdx.z;
    const __half* Q = g_proj[0] + ((size_t)b * T + qt * QROWS) * E + h * 64;
    const __half* K = g_proj[1] + (size_t)b * T * E + h * 64;
    const __half* V = g_proj[2] + (size_t)b * T * E + h * 64;

    int tid = threadIdx.x, lane = tid & 31, wid = tid >> 5;   // wid 0..7
    int g = lane >> 2, t = lane & 3;
    int lm = lane >> 3;
    int krow = (lm >> 1) * 8 + (lane & 7), kcol = (lm & 1) * 8;

    auto loadKV = [&](int buf, int kt) {
        __half* Kd = KV + buf * KVSTRIDE;
        __half* Vd = Kd + 64 * ST2;
        const __half* Kg = K + (size_t)(kt * 64) * E;
        const __half* Vg = V + (size_t)(kt * 64) * E;
        #pragma unroll
        for (int i = 0; i < 2; i++) {
            int idx = tid + i * 256; int r = idx >> 3, c8 = idx & 7;
            cpasync16(&Kd[r * ST2 + c8 * 8], Kg + (size_t)r * E + c8 * 8);
            cpasync16(&Vd[r * ST2 + c8 * 8], Vg + (size_t)r * E + c8 * 8);
        }
        CP_COMMIT();
    };

    int nkv = 2 * qt + 2;

    // Q tile; ones-column pad only in stage 0 (fragment is hoisted, constant)
    #pragma unroll
    for (int i = 0; i < 4; i++) {
        int idx = tid + i * 256; int r = idx >> 3, c8 = idx & 7;
        *(uint4*)&Qs[r * ST2 + c8 * 8] = *(const uint4*)(Q + (size_t)r * E + c8 * 8);
    }
    if (tid < 16) {
        uint4 ones = {0x00003C00u, 0u, 0u, 0u};   // {1.0h, 0...}
        *(uint4*)&KV[64 * ST2 + tid * ST2 + 64] = ones;   // stage 0 V pad rows 0..15
    }
    loadKV(0, 0);
    if (1 < nkv) loadKV(1, 1);
    __syncthreads();

    // hoisted constant ones-column B-fragment (k16 x n8, col0 = 1)
    uint32_t bfl[2];
    ldsm_x2_t(bfl[0], bfl[1],
              kv_u + (((64 + (lane & 15)) * ST2 + 64) << 1));  // V region of stage 0

    // Q fragments (one 16-row m-tile per warp), scaled by SCALE*log2e
    const float QS = SCALE * 1.44269504f;
    uint32_t qf[4][4];
    int mr = wid * 16;
    #pragma unroll
    for (int ks = 0; ks < 4; ks++) {
        int k0 = ks * 16;
        #pragma unroll
        for (int j = 0; j < 4; j++) {
            int rr0 = (j & 1) ? 8 : 0;
            int cc  = (j & 2) ? 8 : 0;
            float2 f = __half22float2(*(const __half2*)&Qs[(mr + g + rr0) * ST2 + k0 + 2 * t + cc]);
            qf[ks][j] = h2u(__floats2half2_rn(f.x * QS, f.y * QS));
        }
    }

    float o[8][4] = {};
    float lacc[4] = {};
    int pr = mr + g;
    int row0 = qt * QROWS + pr;

    for (int kt = 0; kt < nkv; kt++) {
        if (kt + 1 < nkv) { CP_WAIT1(); } else { CP_WAIT0(); }
        __syncthreads();                       // stage kt ready; stage (kt-1)%3 free
        if (kt + 2 < nkv) loadKV((kt + 2) % 3, kt + 2);

        bool active = !(kt == 2 * qt + 1 && wid < 4);
        if (active) {
            uint32_t kb_u = kv_u + (kt % 3) * KVSTRIDE * 2;
            uint32_t vb_u = kb_u + 64 * ST2 * 2;

            // S = Q @ K^T
            float s[8][4] = {};
            #pragma unroll
            for (int ks = 0; ks < 4; ks++) {
                int k0 = ks * 16;
                uint32_t bf[8][2];
                #pragma unroll
                for (int i = 0; i < 4; i++)
                    ldsm_x4(bf[2 * i][0], bf[2 * i][1], bf[2 * i + 1][0], bf[2 * i + 1][1],
                            kb_u + (((i * 16 + krow) * ST2 + k0 + kcol) << 1));
                #pragma unroll
                for (int nt = 0; nt < 8; nt++)
                    mma16(s[nt], qf[ks], bf[nt]);
            }

            if (kt >= 2 * qt) {
                #pragma unroll
                for (int nt = 0; nt < 8; nt++) {
                    int c = kt * 64 + nt * 8 + 2 * t;
                    if (c     > row0)     s[nt][0] = -1e30f;
                    if (c + 1 > row0)     s[nt][1] = -1e30f;
                    if (c     > row0 + 8) s[nt][2] = -1e30f;
                    if (c + 1 > row0 + 8) s[nt][3] = -1e30f;
                }
            }

            // fixed-max softmax: p = 2^s in fp16x2 == PV A-fragment
            uint32_t af[4][4];
            #pragma unroll
            for (int ks = 0; ks < 4; ks++) {
                af[ks][0] = h2ex2(h2u(__floats2half2_rn(s[2 * ks][0],     s[2 * ks][1])));
                af[ks][1] = h2ex2(h2u(__floats2half2_rn(s[2 * ks][2],     s[2 * ks][3])));
                af[ks][2] = h2ex2(h2u(__floats2half2_rn(s[2 * ks + 1][0], s[2 * ks + 1][1])));
                af[ks][3] = h2ex2(h2u(__floats2half2_rn(s[2 * ks + 1][2], s[2 * ks + 1][3])));
            }

            // O += P @ V ; l += P @ ones (constant hoisted fragment)
            #pragma unroll
            for (int ks = 0; ks < 4; ks++) {
                int k0 = ks * 16;
                #pragma unroll
                for (int ntp = 0; ntp < 4; ntp++) {
                    uint32_t b0, b1, b2, b3;
                    uint32_t addr = vb_u +
                        (((k0 + (lane & 15)) * ST2 + (ntp * 2 + (lane >> 4)) * 8) << 1);
                    ldsm_x4_t(b0, b1, b2, b3, addr);
                    uint32_t bfA[2] = {b0, b1}, bfB[2] = {b2, b3};
                    mma16(o[ntp * 2],     af[ks], bfA);
                    mma16(o[ntp * 2 + 1], af[ks], bfB);
                }
                mma16(lacc, af[ks], bfl);
            }
        }
    }

    float la = __shfl_sync(0xffffffffu, lacc[0], lane & 28);
    float lb = __shfl_sync(0xffffffffu, lacc[2], lane & 28);
    float ia = 1.f / la, ib = 1.f / lb;
    __half* O0 = g_att + ((size_t)b * T + row0) * E + h * 64;
    #pragma unroll
    for (int nt = 0; nt < 8; nt++) {
        *(__half2*)&O0[nt * 8 + 2 * t] =
            __floats2half2_rn(o[nt][0] * ia, o[nt][1] * ia);
        *(__half2*)&O0[8 * (size_t)E + nt * 8 + 2 * t] =
            __floats2half2_rn(o[nt][2] * ib, o[nt][3] * ib);
    }
}

// ---------------- launch ----------------
extern "C" void kernel_launch(void* const* d_in, const int* in_sizes, int n_in,
                              void* d_out, int out_size)
{
    const float* v    = (const float*)d_in[0];
    const float* k    = (const float*)d_in[1];
    const float* q    = (const float*)d_in[2];
    const float* ln_g = (const float*)d_in[3];
    const float* ln_b = (const float*)d_in[4];
    const float* Wq   = (const float*)d_in[5];
    const float* Wk   = (const float*)d_in[6];
    const float* Wv   = (const float*)d_in[7];
    const float* Wp   = (const float*)d_in[8];
    const float* bp   = (const float*)d_in[9];
    float* out = (float*)d_out;

    cudaFuncSetAttribute(gemm_qkv, cudaFuncAttributeMaxDynamicSharedMemorySize, GEMM_SMEM);
    cudaFuncSetAttribute(gemm_out, cudaFuncAttributeMaxDynamicSharedMemorySize, GEMM_SMEM);
    cudaFuncSetAttribute(attn_tc,  cudaFuncAttributeMaxDynamicSharedMemorySize, ATT_SMEM);

    // 0) weight transpose->fp16 + LayerNorm->fp16
    round_wT<<<dim3(E / 32, E / 32, 4), 256>>>(Wq, Wk, Wv, Wp);
    ln_kernel<<<dim3(BT, 3), 256>>>(q, k, v, ln_g, ln_b);

    // 1) QKV projections (fp16, 512 thr, 2-stage), fused
    gemm_qkv<<<dim3(E / BN, BT / BM, 3), 512, GEMM_SMEM>>>();

    // 2) causal flash attention (128-row Q tiles, 3-stage ring, hoisted ones-frag)
    attn_tc<<<dim3(T / QROWS, H, B), 256, ATT_SMEM>>>();

    // 3) output projection + bias -> d_out
    gemm_out<<<dim3(E / BN, BT / BM), 512, GEMM_SMEM>>>(bp, out);
}